// round 11
// baseline (speedup 1.0000x reference)
#include <cuda_runtime.h>
#include <cuda_bf16.h>
#include <cstdint>

#define Bn 1024
#define Sn 128
#define Dn 768
#define Cn 56
#define KC 16
#define NG 4                           /* k-groups of 8 warps */
#define CPG 12                         /* chunks per row per group */
#define NBUF 5
#define GRID 148
#define EXTRA 136                      /* 1024 - 148*6 */
#define AST (Sn * KC)                  /* floats per A stage = 2048 (8KB) */
#define BROW 16
#define BST (Cn * BROW)                /* 896 bf16 per B stage */
#define A_BYTES (NG * NBUF * AST * 4)  /* 163840 */
#define B_BYTES (NG * NBUF * BST * 2)  /* 35840  */
#define SMEM_DYN (A_BYTES + B_BYTES)   /* 199680 */

// Raw bf16 weight matrix W[c][k], physical k order.
// Fragment mapping: a0/bb.x <-> phys cols {4t4,4t4+1}, a2/bb.y <-> {4t4+2,4t4+3}.
__device__ __nv_bfloat16 g_Wb[Cn * Dn];

__global__ void build_w_kernel(const float* __restrict__ w2, const float* __restrict__ w3,
                               const float* __restrict__ w4, const float* __restrict__ w5) {
    int i = blockIdx.x * blockDim.x + threadIdx.x;
    if (i >= Cn * Dn) return;
    int c = i / Dn, d = i % Dn;
    float v;
    if (c < 8)       { int f = c / 2;        int j = c % 2;        v = w2[(f * Dn + d) * 2 + j]; }
    else if (c < 20) { int cc = c - 8;  int f = cc / 3; int j = cc % 3; v = w3[(f * Dn + d) * 3 + j]; }
    else if (c < 36) { int cc = c - 20; int f = cc / 4; int j = cc % 4; v = w4[(f * Dn + d) * 4 + j]; }
    else             { int cc = c - 36; int f = cc / 5; int j = cc % 5; v = w5[(f * Dn + d) * 5 + j]; }
    g_Wb[c * Dn + d] = __float2bfloat16(v);
}

__device__ __forceinline__ uint32_t f2bf2(float lo, float hi) {
    __nv_bfloat162 h = __float22bfloat162_rn(make_float2(lo, hi));
    return *reinterpret_cast<uint32_t*>(&h);
}

__device__ __forceinline__ void cp16(uint32_t dst_smem, const void* src) {
    asm volatile("cp.async.cg.shared.global [%0], [%1], 16;\n" :: "r"(dst_smem), "l"(src));
}

__global__ __launch_bounds__(1024, 1) void fused_kernel(
    const int* __restrict__ x, const float* __restrict__ hidden,
    const float* __restrict__ b2, const float* __restrict__ b3,
    const float* __restrict__ b4, const float* __restrict__ b5,
    const float* __restrict__ fcw, const float* __restrict__ fcb,
    float* __restrict__ out)
{
    extern __shared__ __align__(16) unsigned char sraw[];
    float* As = reinterpret_cast<float*>(sraw);                            // [NG][NBUF][128][16]
    __nv_bfloat16* Bsm = reinterpret_cast<__nv_bfloat16*>(sraw + A_BYTES); // [NG][NBUF][56][16]

    __shared__ float Psm[Sn][Cn + 1];      // separate: never aliased -> pipeline never drains
    __shared__ int order[Sn];
    __shared__ unsigned mask4[4];
    __shared__ int sh_len;
    __shared__ float feats[16];

    const int tid  = threadIdx.x;
    const int warp = tid >> 5;
    const int lane = tid & 31;
    const int kg   = warp >> 3;    // k-group 0..3
    const int mw   = warp & 7;     // m-warp within group
    const int l    = tid & 255;    // group-local thread id
    const int g    = lane >> 2;
    const int t4   = lane & 3;
    const int barid = 1 + kg;

    const uint32_t a_gbase = (uint32_t)__cvta_generic_to_shared(As + kg * NBUF * AST);
    const uint32_t b_gbase = (uint32_t)__cvta_generic_to_shared(Bsm + kg * NBUF * BST);

    // staging offsets within a stage (group-local)
    const int  ar0 = l >> 2, aq0 = l & 3;
    const uint32_t a_d0 = (uint32_t)(ar0 * KC + 4 * aq0) * 4;
    const uint32_t a_d1 = a_d0 + (uint32_t)(64 * KC) * 4;
    const long a_o0 = (long)ar0 * Dn + 4 * aq0;
    const long a_o1 = a_o0 + 64L * Dn;
    const int  brw = l >> 1, bq = l & 1;
    const uint32_t b_d = (uint32_t)(brw * BROW + 8 * bq) * 2;
    const __nv_bfloat16* b_s = g_Wb + brw * Dn + 8 * bq;

    // row schedule: bid<EXTRA -> 7 rows, else 6
    int base, nrows;
    if (blockIdx.x < EXTRA) { base = 7 * blockIdx.x;                     nrows = 7; }
    else                    { base = 7 * EXTRA + 6 * (blockIdx.x - EXTRA); nrows = 6; }

    // continuous issue cursor (crosses row boundaries; dummies at the end)
    int ir = 0, ic = 0;
    const int kbase = CPG * kg;    // this group's first chunk within a row

    auto issue = [&](int slot) {
        if (ir < nrows) {
            const float* hsrc = hidden + (long)(base + ir) * (Sn * Dn) + (kbase + ic) * KC;
            cp16(a_gbase + (uint32_t)(slot * AST * 4) + a_d0, hsrc + a_o0);
            cp16(a_gbase + (uint32_t)(slot * AST * 4) + a_d1, hsrc + a_o1);
            if (l < 112)
                cp16(b_gbase + (uint32_t)(slot * BST * 2) + b_d, b_s + (kbase + ic) * KC);
            if (++ic == CPG) { ic = 0; ++ir; }
        }
        asm volatile("cp.async.commit_group;\n");   // empty group if past end
    };

    issue(0); issue(1); issue(2); issue(3);

    float acc[7][4];
    #pragma unroll
    for (int j = 0; j < 7; j++)
        #pragma unroll
        for (int q = 0; q < 4; q++) acc[j][q] = 0.0f;

    const int rowA = mw * 16 + g;
    const uint32_t a_off0 = (uint32_t)(rowA * KC + 4 * t4);
    const uint32_t a_off1 = a_off0 + 8 * KC;
    const float* Agrp = As + kg * NBUF * AST;
    const __nv_bfloat16* Bgrp = Bsm + kg * NBUF * BST;

    int cbuf = 0, nbf = 4;

    #pragma unroll 1
    for (int r = 0; r < nrows; r++) {
        #pragma unroll 1
        for (int c = 0; c < CPG; c++) {
            asm volatile("cp.async.wait_group 3;\n" ::: "memory");
            asm volatile("bar.sync %0, %1;\n" :: "r"(barid), "r"(256) : "memory");
            issue(nbf); nbf = (nbf + 1 == NBUF) ? 0 : nbf + 1;

            const float* Abuf = Agrp + cbuf * AST;
            const __nv_bfloat16* Bbuf = Bgrp + cbuf * BST;
            float4 f0 = *(const float4*)(Abuf + a_off0);
            float4 f1 = *(const float4*)(Abuf + a_off1);
            uint32_t a0 = f2bf2(f0.x, f0.y), a2 = f2bf2(f0.z, f0.w);
            uint32_t a1 = f2bf2(f1.x, f1.y), a3 = f2bf2(f1.z, f1.w);
            #pragma unroll
            for (int j = 0; j < 7; j++) {
                uint2 bb = *(const uint2*)(Bbuf + (8 * j + g) * BROW + 4 * t4);
                asm volatile(
                    "mma.sync.aligned.m16n8k16.row.col.f32.bf16.bf16.f32 "
                    "{%0,%1,%2,%3}, {%4,%5,%6,%7}, {%8,%9}, {%0,%1,%2,%3};\n"
                    : "+f"(acc[j][0]), "+f"(acc[j][1]), "+f"(acc[j][2]), "+f"(acc[j][3])
                    : "r"(a0), "r"(a1), "r"(a2), "r"(a3), "r"(bb.x), "r"(bb.y));
            }
            cbuf = (cbuf + 1 == NBUF) ? 0 : cbuf + 1;
        }

        // ---------------- epilogue for row b (pipeline keeps prefetching row r+1) ----
        const int b = base + r;
        __syncthreads();                                     // S0: all groups done row r

        if (tid < Sn) {
            int nz = (x[b * Sn + tid] != 0);
            unsigned m = __ballot_sync(0xFFFFFFFFu, nz);
            if (lane == 0) mask4[warp] = m;
        }
        if (kg == 0) {
            #pragma unroll
            for (int j = 0; j < 7; j++) {
                int cc = j * 8 + 2 * t4;
                Psm[rowA][cc]         = acc[j][0];
                Psm[rowA][cc + 1]     = acc[j][1];
                Psm[rowA + 8][cc]     = acc[j][2];
                Psm[rowA + 8][cc + 1] = acc[j][3];
            }
        }
        __syncthreads();                                     // S1

        if (tid < Sn) {
            unsigned mw4 = mask4[warp];
            int nzbefore = __popc(mw4 & ((1u << lane) - 1u));
            int nztot_before = 0, total = 0;
            #pragma unroll
            for (int w = 0; w < 4; w++) { if (w < warp) nztot_before += __popc(mask4[w]); total += __popc(mask4[w]); }
            int isnz = (mw4 >> lane) & 1;
            int pos = isnz ? (nztot_before + nzbefore)
                           : (total + (tid - nztot_before - nzbefore));
            order[pos] = tid;
            if (tid == 0) sh_len = total;
        }
        if (kg == 1) {
            #pragma unroll
            for (int j = 0; j < 7; j++) {
                int cc = j * 8 + 2 * t4;
                Psm[rowA][cc]         += acc[j][0];
                Psm[rowA][cc + 1]     += acc[j][1];
                Psm[rowA + 8][cc]     += acc[j][2];
                Psm[rowA + 8][cc + 1] += acc[j][3];
            }
        }
        __syncthreads();                                     // S2
        if (kg == 2) {
            #pragma unroll
            for (int j = 0; j < 7; j++) {
                int cc = j * 8 + 2 * t4;
                Psm[rowA][cc]         += acc[j][0];
                Psm[rowA][cc + 1]     += acc[j][1];
                Psm[rowA + 8][cc]     += acc[j][2];
                Psm[rowA + 8][cc + 1] += acc[j][3];
            }
        }
        __syncthreads();                                     // S3
        if (kg == 3) {
            #pragma unroll
            for (int j = 0; j < 7; j++) {
                int cc = j * 8 + 2 * t4;
                Psm[rowA][cc]         += acc[j][0];
                Psm[rowA][cc + 1]     += acc[j][1];
                Psm[rowA + 8][cc]     += acc[j][2];
                Psm[rowA + 8][cc + 1] += acc[j][3];
            }
        }
        __syncthreads();                                     // S4

        if (warp < 16) {
            int fi = warp;                                   // feature index 0..15
            int kk = fi / 4 + 2;
            int f  = fi % 4;
            int cb = (kk == 2 ? 0 : (kk == 3 ? 8 : (kk == 4 ? 20 : 36))) + f * kk;
            const float* bptr = (kk == 2 ? b2 : (kk == 3 ? b3 : (kk == 4 ? b4 : b5)));
            float bias = bptr[f];
            int nt = sh_len - kk + 1;
            float m = -1e30f;
            for (int tp = lane; tp < nt; tp += 32) {
                float sconv = bias;
                for (int j = 0; j < kk; j++)
                    sconv += Psm[order[tp + j]][cb + j];
                m = fmaxf(m, sconv);
            }
            #pragma unroll
            for (int off = 16; off; off >>= 1)
                m = fmaxf(m, __shfl_xor_sync(0xFFFFFFFFu, m, off));
            if (lane == 0) feats[fi] = m;
        }
        __syncthreads();                                     // S5

        if (tid == 0) {
            float z = fcb[0];
            #pragma unroll
            for (int i = 0; i < 16; i++) z += feats[i] * fcw[i];
            out[b] = 1.0f / (1.0f + expf(-z));
        }

        // reset accumulators for next row (own registers; no barrier needed)
        #pragma unroll
        for (int j = 0; j < 7; j++)
            #pragma unroll
            for (int q = 0; q < 4; q++) acc[j][q] = 0.0f;
    }

    asm volatile("cp.async.wait_group 0;\n" ::: "memory");   // retire dangling dummies
}

extern "C" void kernel_launch(void* const* d_in, const int* in_sizes, int n_in,
                              void* d_out, int out_size) {
    const int*   x      = (const int*)d_in[0];
    const float* hidden = (const float*)d_in[1];
    const float* w2     = (const float*)d_in[2];
    const float* b2     = (const float*)d_in[3];
    const float* w3     = (const float*)d_in[4];
    const float* b3     = (const float*)d_in[5];
    const float* w4     = (const float*)d_in[6];
    const float* b4     = (const float*)d_in[7];
    const float* w5     = (const float*)d_in[8];
    const float* b5     = (const float*)d_in[9];
    const float* fcw    = (const float*)d_in[10];
    const float* fcb    = (const float*)d_in[11];
    float* out = (float*)d_out;

    cudaFuncSetAttribute(fused_kernel, cudaFuncAttributeMaxDynamicSharedMemorySize, SMEM_DYN);

    build_w_kernel<<<(Cn * Dn + 255) / 256, 256>>>(w2, w3, w4, w5);
    fused_kernel<<<GRID, 1024, SMEM_DYN>>>(x, hidden, b2, b3, b4, b5, fcw, fcb, out);
}

// round 12
// speedup vs baseline: 1.0222x; 1.0222x over previous
#include <cuda_runtime.h>
#include <cuda_bf16.h>
#include <cuda_fp16.h>
#include <cstdint>

#define Bn 1024
#define Sn 128
#define Dn 768
#define Cn 56
#define KC 16
#define NCHUNK 48
#define NBUF 4
#define DIST 3
#define GRID 592                      /* 148 SMs x 4 CTAs, all resident */
#define NR2 432                       /* CTAs with 2 rows; rest have 1 */
#define AST (Sn * KC)                 /* floats per A stage = 2048 (8KB) */
#define BROW 16                       /* bf16 per B row, 32B stride */
#define BST (Cn * BROW)               /* 896 bf16 per B stage */
#define A_BYTES (NBUF * AST * 4)      /* 32768 */
#define B_BYTES (NBUF * BST * 2)      /* 7168  */
#define SMEM_DYN (A_BYTES + B_BYTES)  /* 39936 */

// Raw bf16 weight matrix W[c][k], physical k order.
// Fragment mapping: a0/bb.x <-> phys cols {4t4,4t4+1}, a2/bb.y <-> {4t4+2,4t4+3}.
__device__ __nv_bfloat16 g_Wb[Cn * Dn];

__global__ void build_w_kernel(const float* __restrict__ w2, const float* __restrict__ w3,
                               const float* __restrict__ w4, const float* __restrict__ w5) {
    int i = blockIdx.x * blockDim.x + threadIdx.x;
    if (i >= Cn * Dn) return;
    int c = i / Dn, d = i % Dn;
    float v;
    if (c < 8)       { int f = c / 2;        int j = c % 2;        v = w2[(f * Dn + d) * 2 + j]; }
    else if (c < 20) { int cc = c - 8;  int f = cc / 3; int j = cc % 3; v = w3[(f * Dn + d) * 3 + j]; }
    else if (c < 36) { int cc = c - 20; int f = cc / 4; int j = cc % 4; v = w4[(f * Dn + d) * 4 + j]; }
    else             { int cc = c - 36; int f = cc / 5; int j = cc % 5; v = w5[(f * Dn + d) * 5 + j]; }
    g_Wb[c * Dn + d] = __float2bfloat16(v);
}

__device__ __forceinline__ uint32_t f2bf2(float lo, float hi) {
    __nv_bfloat162 h = __float22bfloat162_rn(make_float2(lo, hi));
    return *reinterpret_cast<uint32_t*>(&h);
}

__device__ __forceinline__ void cp16(uint32_t dst_smem, const void* src) {
    asm volatile("cp.async.cg.shared.global [%0], [%1], 16;\n" :: "r"(dst_smem), "l"(src));
}

__global__ __launch_bounds__(256, 4) void fused_kernel(
    const int* __restrict__ x, const float* __restrict__ hidden,
    const float* __restrict__ b2, const float* __restrict__ b3,
    const float* __restrict__ b4, const float* __restrict__ b5,
    const float* __restrict__ fcw, const float* __restrict__ fcb,
    float* __restrict__ out)
{
    extern __shared__ __align__(16) unsigned char sraw[];
    float* As = reinterpret_cast<float*>(sraw);                            // [NBUF][128][16]
    __nv_bfloat16* Bsm = reinterpret_cast<__nv_bfloat16*>(sraw + A_BYTES); // [NBUF][56][16]

    __shared__ __half Psm[Sn][58];         // fp16 P exchange (non-aliased -> pipeline never drains)
    __shared__ int order[Sn];
    __shared__ unsigned mask4[4];
    __shared__ int sh_len;
    __shared__ float feats[16];

    const int tid  = threadIdx.x;
    const int warp = tid >> 5;
    const int lane = tid & 31;
    const int g    = lane >> 2;   // 0..7
    const int t4   = lane & 3;    // 0..3

    const uint32_t a_base = (uint32_t)__cvta_generic_to_shared(As);
    const uint32_t b_base = (uint32_t)__cvta_generic_to_shared(Bsm);

    // hoisted per-thread staging offsets (row-relative)
    const int  ar0 = tid >> 2, aq0 = tid & 3;
    const uint32_t a_d0 = (uint32_t)(ar0 * KC + 4 * aq0) * 4;
    const uint32_t a_d1 = a_d0 + (uint32_t)(64 * KC) * 4;
    const long a_o0 = (long)ar0 * Dn + 4 * aq0;
    const long a_o1 = a_o0 + 64L * Dn;
    const int  brw = tid >> 1, bq = tid & 1;
    const uint32_t b_d = (uint32_t)(brw * BROW + 8 * bq) * 2;
    const __nv_bfloat16* b_s = g_Wb + brw * Dn + 8 * bq;

    const int rowA = warp * 16 + g;
    const uint32_t a_off0 = (uint32_t)(rowA * KC + 4 * t4);
    const uint32_t a_off1 = a_off0 + 8 * KC;

    // row schedule: bid<NR2 -> rows {2bid, 2bid+1}, else row {NR2+bid}
    int row0, nrows;
    if (blockIdx.x < NR2) { row0 = 2 * blockIdx.x; nrows = 2; }
    else                  { row0 = NR2 + blockIdx.x; nrows = 1; }

    // continuous issue cursor across rows (empty commit-groups past the end)
    int ir = 0, ic = 0;
    auto issue = [&](int slot) {
        if (ir < nrows) {
            const float* hsrc = hidden + (long)(row0 + ir) * (Sn * Dn) + ic * KC;
            cp16(a_base + (uint32_t)(slot * AST * 4) + a_d0, hsrc + a_o0);
            cp16(a_base + (uint32_t)(slot * AST * 4) + a_d1, hsrc + a_o1);
            if (tid < 112)
                cp16(b_base + (uint32_t)(slot * BST * 2) + b_d, b_s + ic * KC);
            if (++ic == NCHUNK) { ic = 0; ++ir; }
        }
        asm volatile("cp.async.commit_group;\n");
    };

    issue(0); issue(1); issue(2);

    int cbuf = 0, nbf = DIST;

    #pragma unroll 1
    for (int r = 0; r < nrows; r++) {
        float acc[7][4];
        #pragma unroll
        for (int j = 0; j < 7; j++)
            #pragma unroll
            for (int q = 0; q < 4; q++) acc[j][q] = 0.0f;

        #pragma unroll 1
        for (int ci = 0; ci < NCHUNK; ci++) {
            asm volatile("cp.async.wait_group 2;\n" ::: "memory");
            __syncthreads();
            issue(nbf); nbf = (nbf + 1) & (NBUF - 1);

            const float* Abuf = As + cbuf * AST;
            const __nv_bfloat16* Bbuf = Bsm + cbuf * BST;
            float4 f0 = *(const float4*)(Abuf + a_off0);
            float4 f1 = *(const float4*)(Abuf + a_off1);
            uint32_t a0 = f2bf2(f0.x, f0.y), a2 = f2bf2(f0.z, f0.w);
            uint32_t a1 = f2bf2(f1.x, f1.y), a3 = f2bf2(f1.z, f1.w);
            #pragma unroll
            for (int j = 0; j < 7; j++) {
                uint2 bb = *(const uint2*)(Bbuf + (8 * j + g) * BROW + 4 * t4);
                asm volatile(
                    "mma.sync.aligned.m16n8k16.row.col.f32.bf16.bf16.f32 "
                    "{%0,%1,%2,%3}, {%4,%5,%6,%7}, {%8,%9}, {%0,%1,%2,%3};\n"
                    : "+f"(acc[j][0]), "+f"(acc[j][1]), "+f"(acc[j][2]), "+f"(acc[j][3])
                    : "r"(a0), "r"(a1), "r"(a2), "r"(a3), "r"(bb.x), "r"(bb.y));
            }
            cbuf = (cbuf + 1) & (NBUF - 1);
        }

        // -------- epilogue for row b (pipeline keeps prefetching next row) --------
        const int b = row0 + r;

        // spill acc -> fp16 Psm (each warp owns its 16 rows) + ballot phase
        #pragma unroll
        for (int j = 0; j < 7; j++) {
            int c = j * 8 + 2 * t4;
            Psm[rowA][c]         = __float2half_rn(acc[j][0]);
            Psm[rowA][c + 1]     = __float2half_rn(acc[j][1]);
            Psm[rowA + 8][c]     = __float2half_rn(acc[j][2]);
            Psm[rowA + 8][c + 1] = __float2half_rn(acc[j][3]);
        }
        if (tid < Sn) {
            int nz = (x[b * Sn + tid] != 0);
            unsigned m = __ballot_sync(0xFFFFFFFFu, nz);
            if (lane == 0) mask4[warp] = m;
        }
        __syncthreads();

        if (tid < Sn) {
            unsigned mw = mask4[warp];
            int nzbefore = __popc(mw & ((1u << lane) - 1u));
            int nztot_before = 0, total = 0;
            #pragma unroll
            for (int w = 0; w < 4; w++) { if (w < warp) nztot_before += __popc(mask4[w]); total += __popc(mask4[w]); }
            int isnz = (mw >> lane) & 1;
            int pos = isnz ? (nztot_before + nzbefore)
                           : (total + (tid - nztot_before - nzbefore));
            order[pos] = tid;
            if (tid == 0) sh_len = total;
        }
        __syncthreads();

        // ragged conv + max-pool: 16 features, 2 per warp
        const int L = sh_len;
        #pragma unroll
        for (int rr = 0; rr < 2; rr++) {
            int fi = warp + rr * 8;
            int kk = fi / 4 + 2;
            int f  = fi % 4;
            int cb = (kk == 2 ? 0 : (kk == 3 ? 8 : (kk == 4 ? 20 : 36))) + f * kk;
            const float* bptr = (kk == 2 ? b2 : (kk == 3 ? b3 : (kk == 4 ? b4 : b5)));
            float bias = bptr[f];
            int nt = L - kk + 1;
            float m = -1e30f;
            for (int tp = lane; tp < nt; tp += 32) {
                float sconv = bias;
                for (int j = 0; j < kk; j++)
                    sconv += __half2float(Psm[order[tp + j]][cb + j]);
                m = fmaxf(m, sconv);
            }
            #pragma unroll
            for (int off = 16; off; off >>= 1)
                m = fmaxf(m, __shfl_xor_sync(0xFFFFFFFFu, m, off));
            if (lane == 0) feats[fi] = m;
        }
        __syncthreads();

        if (tid == 0) {
            float z = fcb[0];
            #pragma unroll
            for (int i = 0; i < 16; i++) z += feats[i] * fcw[i];
            out[b] = 1.0f / (1.0f + expf(-z));
        }
    }

    asm volatile("cp.async.wait_group 0;\n" ::: "memory");   // retire trailing empty groups
}

extern "C" void kernel_launch(void* const* d_in, const int* in_sizes, int n_in,
                              void* d_out, int out_size) {
    const int*   x      = (const int*)d_in[0];
    const float* hidden = (const float*)d_in[1];
    const float* w2     = (const float*)d_in[2];
    const float* b2     = (const float*)d_in[3];
    const float* w3     = (const float*)d_in[4];
    const float* b3     = (const float*)d_in[5];
    const float* w4     = (const float*)d_in[6];
    const float* b4     = (const float*)d_in[7];
    const float* w5     = (const float*)d_in[8];
    const float* b5     = (const float*)d_in[9];
    const float* fcw    = (const float*)d_in[10];
    const float* fcb    = (const float*)d_in[11];
    float* out = (float*)d_out;

    cudaFuncSetAttribute(fused_kernel, cudaFuncAttributeMaxDynamicSharedMemorySize, SMEM_DYN);

    build_w_kernel<<<(Cn * Dn + 255) / 256, 256>>>(w2, w3, w4, w5);
    fused_kernel<<<GRID, 256, SMEM_DYN>>>(x, hidden, b2, b3, b4, b5, fcw, fcb, out);
}